// round 11
// baseline (speedup 1.0000x reference)
#include <cuda_runtime.h>
#include <cuda_bf16.h>
#include <float.h>
#include <math.h>

// Problem shape (fixed by reference setup_inputs)
#define B_   16
#define C_   256
#define H_   128
#define W_   128
#define HW_  (H_ * W_)           // 16384
#define HW4_ (HW_ / 4)           // 4096 float4 columns per image

// Scratch: feat [B, 2, H, W]  (avg then max)
__device__ float g_feat[B_ * 2 * HW_];
// Per-row produced counter (row ready at 2) and consumed counter.
// Zero at load; consumed-count protocol resets both -> graph-replay clean.
__device__ int g_prod[B_ * H_];
__device__ int g_done[B_ * H_];

// ---------------------------------------------------------------------------
// Kernel 1: channel-wise mean + max over C=256.  (R6 config — best measured)
// Block = half a spatial row: (16 float4 cols) x (16 channel-splits of 16 ch).
// 4096 blocks x 256 threads, full unroll (high MLP is a win per R10).
// Adds one fence + one atomic per block to publish its half-row.
// ---------------------------------------------------------------------------
__global__ __launch_bounds__(256) void reduce_mean_max_kernel(
    const float* __restrict__ x)
{
    cudaTriggerProgrammaticLaunchCompletion();

    __shared__ float4 s_sum[256];
    __shared__ float4 s_max[256];

    const int tid  = threadIdx.x;
    const int col  = tid & 15;                 // float4 column within half-row
    const int cs   = tid >> 4;                 // channel split 0..15

    const int blk    = blockIdx.x;             // 0..4095
    const int row_id = blk >> 1;               // 0..2047 == b*128 + h
    const int half   = blk & 1;
    const int b      = row_id >> 7;
    const int h      = row_id & 127;
    const int hw4    = (h << 5) + (half << 4) + col;

    const float4* xb = reinterpret_cast<const float4*>(x)
                     + (size_t)b * C_ * HW4_ + (size_t)(cs * 16) * HW4_ + hw4;

    float4 s = make_float4(0.f, 0.f, 0.f, 0.f);
    float4 m = make_float4(-FLT_MAX, -FLT_MAX, -FLT_MAX, -FLT_MAX);

    #pragma unroll
    for (int c = 0; c < 16; ++c) {
        float4 v = __ldcs(xb + (size_t)c * HW4_);
        s.x += v.x; s.y += v.y; s.z += v.z; s.w += v.w;
        m.x = fmaxf(m.x, v.x); m.y = fmaxf(m.y, v.y);
        m.z = fmaxf(m.z, v.z); m.w = fmaxf(m.w, v.w);
    }

    s_sum[tid] = s;
    s_max[tid] = m;
    __syncthreads();

    if (tid < 16) {
        #pragma unroll
        for (int k = 1; k < 16; ++k) {
            float4 ps = s_sum[tid + k * 16];
            float4 pm = s_max[tid + k * 16];
            s.x += ps.x; s.y += ps.y; s.z += ps.z; s.w += ps.w;
            m.x = fmaxf(m.x, pm.x); m.y = fmaxf(m.y, pm.y);
            m.z = fmaxf(m.z, pm.z); m.w = fmaxf(m.w, pm.w);
        }
        const float inv = 1.0f / (float)C_;
        float4 a = make_float4(s.x * inv, s.y * inv, s.z * inv, s.w * inv);

        float4* fa = reinterpret_cast<float4*>(g_feat)
                   + (size_t)b * 2 * HW4_ + hw4;
        fa[0]    = a;   // channel 0: avg
        fa[HW4_] = m;   // channel 1: max
        __threadfence();   // publish feat half-row before the flag
    }
    __syncthreads();
    if (tid == 0) atomicAdd(&g_prod[row_id], 1);   // row ready at 2
}

// ---------------------------------------------------------------------------
// Kernel 2: 3x3 conv (2 in ch, pad 1, no bias) + sigmoid.
// 1024 blocks x 256 threads, 1 px/thread (best measured conv config).
// PDL early launch; waits only on the 4 row-flags its 2 output rows need,
// polling with volatile reads + 1us nanosleep (no L2 atomic storm).
// ---------------------------------------------------------------------------
__global__ __launch_bounds__(256) void conv_sigmoid_kernel(
    const float* __restrict__ conv_w,   // [1,2,3,3] OIHW
    float* __restrict__ out)            // [B,1,H,W]
{
    const int tid = threadIdx.x;
    const int bid = blockIdx.x;          // 0..1023
    const int b   = bid >> 6;            // 64 blocks per image
    const int h0  = (bid & 63) * 2;      // block covers output rows h0, h0+1

    // Prologue (overlaps producer drain): weights into registers.
    float wk[18];
    #pragma unroll
    for (int i = 0; i < 18; ++i) wk[i] = __ldg(conv_w + i);

    // Wait for producer rows h0-1 .. h0+2 (volatile polls, gentle backoff).
    if (tid == 0) {
        const volatile int* vp = (const volatile int*)g_prod;
        #pragma unroll
        for (int r = h0 - 1; r <= h0 + 2; ++r) {
            if (r < 0 || r >= H_) continue;
            while (vp[b * H_ + r] < 2) __nanosleep(1024);
        }
        __threadfence();   // acquire: order feat reads after flag observation
    }
    __syncthreads();

    const int idx = bid * 256 + tid;     // global pixel id
    const int hw  = idx & (HW_ - 1);
    const int h   = hw >> 7;
    const int w   = hw & (W_ - 1);

    const float* f0 = g_feat + (size_t)b * 2 * HW_;   // avg channel
    const float* f1 = f0 + HW_;                       // max channel

    float acc = 0.f;
    #pragma unroll
    for (int kh = 0; kh < 3; ++kh) {
        const int hh = h + kh - 1;
        if (hh < 0 || hh >= H_) continue;
        #pragma unroll
        for (int kw = 0; kw < 3; ++kw) {
            const int ww = w + kw - 1;
            if (ww < 0 || ww >= W_) continue;
            const int off = hh * W_ + ww;
            acc = fmaf(f0[off], wk[kh * 3 + kw], acc);
            acc = fmaf(f1[off], wk[9 + kh * 3 + kw], acc);
        }
    }

    out[idx] = 1.0f / (1.0f + __expf(-acc));

    // Consumed-count bookkeeping: last consumer of each row resets both
    // counters, so every graph replay starts from zeroed state.
    __syncthreads();   // all feat reads done
    if (tid == 0) {
        #pragma unroll
        for (int r = h0 - 1; r <= h0 + 2; ++r) {
            if (r < 0 || r >= H_) continue;
            const int g = b * H_ + r;
            const int target = (r == 0 || r == H_ - 1) ? 1 : 2;
            if (atomicAdd(&g_done[g], 1) == target - 1) {
                atomicExch(&g_done[g], 0);
                atomicExch(&g_prod[g], 0);
            }
        }
    }
}

// ---------------------------------------------------------------------------
extern "C" void kernel_launch(void* const* d_in, const int* in_sizes, int n_in,
                              void* d_out, int out_size)
{
    const float* x      = (const float*)d_in[0];   // [16,256,128,128] f32
    const float* conv_w = (const float*)d_in[1];   // [1,2,3,3] f32
    float*       out    = (float*)d_out;           // [16,1,128,128] f32

    // Kernel 1: 4096 blocks x 256 threads (R6 best)
    reduce_mean_max_kernel<<<4096, 256>>>(x);

    // Kernel 2: 1024 blocks x 256 threads, PDL early launch + row-flag waits
    cudaLaunchConfig_t cfg = {};
    cfg.gridDim  = dim3((B_ * HW_) / 256, 1, 1);
    cfg.blockDim = dim3(256, 1, 1);
    cfg.dynamicSmemBytes = 0;
    cfg.stream = 0;

    cudaLaunchAttribute attrs[1];
    attrs[0].id = cudaLaunchAttributeProgrammaticStreamSerialization;
    attrs[0].val.programmaticStreamSerializationAllowed = 1;
    cfg.attrs = attrs;
    cfg.numAttrs = 1;

    cudaLaunchKernelEx(&cfg, conv_sigmoid_kernel, conv_w, out);
}

// round 12
// speedup vs baseline: 1.0498x; 1.0498x over previous
#include <cuda_runtime.h>
#include <cuda_bf16.h>
#include <float.h>
#include <math.h>

// Problem shape (fixed by reference setup_inputs)
#define B_   16
#define C_   256
#define H_   128
#define W_   128
#define HW_  (H_ * W_)           // 16384
#define HW4_ (HW_ / 4)           // 4096 float4 columns per image

// Scratch: feat [B, 2, H, W]  (avg then max)
__device__ float g_feat[B_ * 2 * HW_];

// ---------------------------------------------------------------------------
// Kernel 1: channel-wise mean + max over C=256.  (R6 config — best measured,
// byte-identical: 4096 blocks x 256 thr, half-row x 16 splits, full unroll)
// ---------------------------------------------------------------------------
__global__ __launch_bounds__(256) void reduce_mean_max_kernel(
    const float* __restrict__ x)
{
    cudaTriggerProgrammaticLaunchCompletion();

    __shared__ float4 s_sum[256];
    __shared__ float4 s_max[256];

    const int tid  = threadIdx.x;
    const int col  = tid & 15;                 // float4 column within half-row
    const int cs   = tid >> 4;                 // channel split 0..15

    const int blk    = blockIdx.x;             // 0..4095
    const int row_id = blk >> 1;               // 0..2047 == b*128 + h
    const int half   = blk & 1;
    const int b      = row_id >> 7;
    const int h      = row_id & 127;
    const int hw4    = (h << 5) + (half << 4) + col;

    const float4* xb = reinterpret_cast<const float4*>(x)
                     + (size_t)b * C_ * HW4_ + (size_t)(cs * 16) * HW4_ + hw4;

    float4 s = make_float4(0.f, 0.f, 0.f, 0.f);
    float4 m = make_float4(-FLT_MAX, -FLT_MAX, -FLT_MAX, -FLT_MAX);

    #pragma unroll
    for (int c = 0; c < 16; ++c) {
        float4 v = __ldcs(xb + (size_t)c * HW4_);
        s.x += v.x; s.y += v.y; s.z += v.z; s.w += v.w;
        m.x = fmaxf(m.x, v.x); m.y = fmaxf(m.y, v.y);
        m.z = fmaxf(m.z, v.z); m.w = fmaxf(m.w, v.w);
    }

    s_sum[tid] = s;
    s_max[tid] = m;
    __syncthreads();

    if (tid < 16) {
        #pragma unroll
        for (int k = 1; k < 16; ++k) {
            float4 ps = s_sum[tid + k * 16];
            float4 pm = s_max[tid + k * 16];
            s.x += ps.x; s.y += ps.y; s.z += ps.z; s.w += ps.w;
            m.x = fmaxf(m.x, pm.x); m.y = fmaxf(m.y, pm.y);
            m.z = fmaxf(m.z, pm.z); m.w = fmaxf(m.w, pm.w);
        }
        const float inv = 1.0f / (float)C_;
        float4 a = make_float4(s.x * inv, s.y * inv, s.z * inv, s.w * inv);

        float4* fa = reinterpret_cast<float4*>(g_feat)
                   + (size_t)b * 2 * HW4_ + hw4;
        fa[0]    = a;   // channel 0: avg
        fa[HW4_] = m;   // channel 1: max
    }
}

// ---------------------------------------------------------------------------
// Kernel 2: 3x3 conv (2 in ch, pad 1, no bias) + sigmoid.
// 8 px/thread: 256 blocks x 128 thr. Per thread: 6 row-segments loaded as
// 2x float4 + 2 halo scalars each (24 independent loads for 8 px = 3/px),
// one L2 round-trip critical path, 2x float4 stores.
// ---------------------------------------------------------------------------
__global__ __launch_bounds__(128) void conv_sigmoid_kernel(
    const float* __restrict__ conv_w,   // [1,2,3,3] OIHW
    float* __restrict__ out)            // [B,1,H,W]
{
    // Prologue (overlaps producer drain): weights into registers.
    float wk[18];
    #pragma unroll
    for (int i = 0; i < 18; ++i) wk[i] = __ldg(conv_w + i);

    cudaGridDependencySynchronize();

    const int idx = blockIdx.x * blockDim.x + threadIdx.x;  // 0..32767
    const int b   = idx >> 11;            // 2048 8px-groups per image
    const int rem = idx & 2047;
    const int h   = rem >> 4;             // row
    const int w0  = (rem & 15) << 3;      // first of 8 pixels

    const float* fb = g_feat + (size_t)b * 2 * HW_;

    float acc[8];
    #pragma unroll
    for (int i = 0; i < 8; ++i) acc[i] = 0.f;

    #pragma unroll
    for (int ch = 0; ch < 2; ++ch) {
        #pragma unroll
        for (int r = 0; r < 3; ++r) {
            const int hh = h + r - 1;
            if (hh < 0 || hh >= H_) continue;
            const float* row = fb + ch * HW_ + hh * W_ + w0;

            float a[10];
            float4 v0 = *reinterpret_cast<const float4*>(row);
            float4 v1 = *reinterpret_cast<const float4*>(row + 4);
            a[0] = (w0 > 0)       ? row[-1] : 0.f;
            a[1] = v0.x; a[2] = v0.y; a[3] = v0.z; a[4] = v0.w;
            a[5] = v1.x; a[6] = v1.y; a[7] = v1.z; a[8] = v1.w;
            a[9] = (w0 + 8 < W_)  ? row[8]  : 0.f;

            const float k0 = wk[ch * 9 + r * 3 + 0];
            const float k1 = wk[ch * 9 + r * 3 + 1];
            const float k2 = wk[ch * 9 + r * 3 + 2];

            #pragma unroll
            for (int i = 0; i < 8; ++i)
                acc[i] = fmaf(a[i], k0, fmaf(a[i + 1], k1,
                         fmaf(a[i + 2], k2, acc[i])));
        }
    }

    float o[8];
    #pragma unroll
    for (int i = 0; i < 8; ++i) o[i] = 1.0f / (1.0f + __expf(-acc[i]));

    float4* op = reinterpret_cast<float4*>(out + (size_t)b * HW_ + h * W_ + w0);
    op[0] = make_float4(o[0], o[1], o[2], o[3]);
    op[1] = make_float4(o[4], o[5], o[6], o[7]);
}

// ---------------------------------------------------------------------------
extern "C" void kernel_launch(void* const* d_in, const int* in_sizes, int n_in,
                              void* d_out, int out_size)
{
    const float* x      = (const float*)d_in[0];   // [16,256,128,128] f32
    const float* conv_w = (const float*)d_in[1];   // [1,2,3,3] f32
    float*       out    = (float*)d_out;           // [16,1,128,128] f32

    // Kernel 1: 4096 blocks x 256 threads (R6 best)
    reduce_mean_max_kernel<<<4096, 256>>>(x);

    // Kernel 2: 256 blocks x 128 threads, PDL-overlapped launch
    cudaLaunchConfig_t cfg = {};
    cfg.gridDim  = dim3(256, 1, 1);
    cfg.blockDim = dim3(128, 1, 1);
    cfg.dynamicSmemBytes = 0;
    cfg.stream = 0;

    cudaLaunchAttribute attrs[1];
    attrs[0].id = cudaLaunchAttributeProgrammaticStreamSerialization;
    attrs[0].val.programmaticStreamSerializationAllowed = 1;
    cfg.attrs = attrs;
    cfg.numAttrs = 1;

    cudaLaunchKernelEx(&cfg, conv_sigmoid_kernel, conv_w, out);
}